// round 1
// baseline (speedup 1.0000x reference)
#include <cuda_runtime.h>
#include <cuda_bf16.h>
#include <math.h>

#define B 32
#define L 256
#define D 512
#define MAX_LEN 2048   // L * MAX_DUR(8)

// Scratch: per-(batch,pos) source row index, -1 => masked (write zeros)
__device__ int g_idx[B * MAX_LEN];

// ---------------------------------------------------------------------------
// Kernel A: per-batch round + inclusive scan + searchsorted for all positions
// 32 blocks x 256 threads (one thread per token)
// ---------------------------------------------------------------------------
__global__ void lr_index_kernel(const float* __restrict__ duration,
                                const void* __restrict__ alpha_ptr)
{
    const int b = blockIdx.x;
    const int t = threadIdx.x;          // 0..255
    const int lane = t & 31;
    const int wid  = t >> 5;            // 0..7

    // --- resolve alpha (int32 or float32, bit-sniffed) ---
    int   ab = *(const int*)alpha_ptr;
    float af = __int_as_float(ab);
    float alpha = (fabsf(af) >= 1e-30f && fabsf(af) <= 1e30f) ? af : (float)ab;

    // --- round (rintf = round-half-to-even, matches jnp.round) ---
    int r = (int)rintf(duration[b * L + t] * alpha);

    // --- inclusive scan over 256 values (warp scan + warp-total scan) ---
    int v = r;
    #pragma unroll
    for (int off = 1; off < 32; off <<= 1) {
        int n = __shfl_up_sync(0xffffffffu, v, off);
        if (lane >= off) v += n;
    }
    __shared__ int warp_tot[8];
    if (lane == 31) warp_tot[wid] = v;
    __syncthreads();
    __shared__ int warp_pre[8];
    if (t < 8) {
        int wv = warp_tot[t];
        #pragma unroll
        for (int off = 1; off < 8; off <<= 1) {
            int n = __shfl_up_sync(0xffu, wv, off);
            if (t >= off) wv += n;
        }
        warp_pre[t] = wv;   // inclusive warp prefix
    }
    __syncthreads();
    int csum = v + (wid > 0 ? warp_pre[wid - 1] : 0);

    __shared__ int s_csum[L];
    s_csum[t] = csum;
    __syncthreads();

    const int total = s_csum[L - 1];

    // --- binary search for 8 positions per thread ---
    // idx = first i with csum[i] > pos  (searchsorted side='right')
    #pragma unroll
    for (int k = 0; k < MAX_LEN / L; k++) {
        int pos = t + k * L;
        int out;
        if (pos >= total) {
            out = -1;                    // masked -> zeros
        } else {
            int lo = 0, hi = L;          // first index with csum[i] > pos
            while (lo < hi) {
                int mid = (lo + hi) >> 1;
                if (s_csum[mid] > pos) hi = mid; else lo = mid + 1;
            }
            out = lo < (L - 1) ? lo : (L - 1);
        }
        g_idx[b * MAX_LEN + pos] = out;
    }
}

// ---------------------------------------------------------------------------
// Kernel B: expansion copy. One block per output row (65536 blocks),
// 128 threads, float4 fully coalesced: 512 floats per row.
// ---------------------------------------------------------------------------
__global__ void __launch_bounds__(128)
lr_expand_kernel(const float* __restrict__ att_out, float* __restrict__ out)
{
    const int row = blockIdx.x;               // 0 .. B*MAX_LEN-1
    const int b = row >> 11;                  // row / 2048
    const int idx = g_idx[row];

    float4* __restrict__ dst = (float4*)(out + (size_t)row * D) + threadIdx.x;

    if (idx < 0) {
        float4 z = make_float4(0.f, 0.f, 0.f, 0.f);
        dst[0] = z;
    } else {
        const float4* __restrict__ src =
            (const float4*)(att_out + ((size_t)b * L + idx) * D) + threadIdx.x;
        dst[0] = __ldg(src);
    }
}

extern "C" void kernel_launch(void* const* d_in, const int* in_sizes, int n_in,
                              void* d_out, int out_size)
{
    const float* att_out  = (const float*)d_in[0];
    const float* duration = (const float*)d_in[1];
    const void*  alpha    = d_in[2];

    lr_index_kernel<<<B, L>>>(duration, alpha);
    lr_expand_kernel<<<B * MAX_LEN, 128>>>(att_out, (float*)d_out);
}

// round 2
// speedup vs baseline: 1.5902x; 1.5902x over previous
#include <cuda_runtime.h>
#include <cuda_bf16.h>
#include <math.h>

#define B 32
#define L 256
#define D 512
#define MAX_LEN 2048          // L * MAX_DUR(8)
#define ROWS_PB 64            // output rows per block
#define BLOCKS_PER_BATCH (MAX_LEN / ROWS_PB)   // 32

// ---------------------------------------------------------------------------
// Fused kernel: each block re-computes the (cheap) per-batch scan, derives the
// source index for its 64 output rows, then does a wide coalesced expand-copy.
// Grid = B * 32 = 1024 blocks x 256 threads (~1 wave on 148 SMs).
// ---------------------------------------------------------------------------
__global__ void __launch_bounds__(256)
lr_fused_kernel(const float* __restrict__ att_out,
                const float* __restrict__ duration,
                const void*  __restrict__ alpha_ptr,
                float* __restrict__ out)
{
    const int b        = blockIdx.x / BLOCKS_PER_BATCH;
    const int row_base = (blockIdx.x % BLOCKS_PER_BATCH) * ROWS_PB;
    const int t    = threadIdx.x;       // 0..255
    const int lane = t & 31;
    const int wid  = t >> 5;            // 0..7

    // --- resolve alpha (int32 or float32, bit-sniffed) ---
    int   ab = *(const int*)alpha_ptr;
    float af = __int_as_float(ab);
    float alpha = (fabsf(af) >= 1e-30f && fabsf(af) <= 1e30f) ? af : (float)ab;

    // --- round (rintf = round-half-even, matches jnp.round) ---
    int r = (int)rintf(__ldg(&duration[b * L + t]) * alpha);

    // --- inclusive scan over 256 values ---
    int v = r;
    #pragma unroll
    for (int off = 1; off < 32; off <<= 1) {
        int n = __shfl_up_sync(0xffffffffu, v, off);
        if (lane >= off) v += n;
    }
    __shared__ int warp_tot[8];
    __shared__ int warp_pre[8];
    if (lane == 31) warp_tot[wid] = v;
    __syncthreads();
    if (t < 8) {
        int wv = warp_tot[t];
        #pragma unroll
        for (int off = 1; off < 8; off <<= 1) {
            int n = __shfl_up_sync(0xffu, wv, off);
            if (t >= off) wv += n;
        }
        warp_pre[t] = wv;
    }
    __syncthreads();
    int csum = v + (wid > 0 ? warp_pre[wid - 1] : 0);

    __shared__ int s_csum[L];
    s_csum[t] = csum;
    __syncthreads();

    const int total = s_csum[L - 1];

    // --- per-row source index for this block's 64 rows ---
    __shared__ int s_idx[ROWS_PB];
    if (t < ROWS_PB) {
        int pos = row_base + t;
        int outi;
        if (pos >= total) {
            outi = -1;                      // masked -> zeros
        } else {
            int lo = 0, hi = L;             // first i with csum[i] > pos
            while (lo < hi) {
                int mid = (lo + hi) >> 1;
                if (s_csum[mid] > pos) hi = mid; else lo = mid + 1;
            }
            outi = lo < (L - 1) ? lo : (L - 1);
        }
        s_idx[t] = outi;
    }
    __syncthreads();

    // --- expand copy: 2 rows per iteration (256 thr = 2 x 128 float4) ---
    const int rl  = t >> 7;                 // 0 or 1: row within pair
    const int col = t & 127;                // float4 column
    float* dst_base = out + ((size_t)b * MAX_LEN + row_base) * D;
    const float* src_batch = att_out + (size_t)b * L * D;

    #pragma unroll 8
    for (int it = 0; it < ROWS_PB / 2; it++) {
        int rloc = it * 2 + rl;
        int idx  = s_idx[rloc];
        float4 val = make_float4(0.f, 0.f, 0.f, 0.f);
        if (idx >= 0)
            val = __ldg((const float4*)(src_batch + (size_t)idx * D) + col);
        __stcs((float4*)(dst_base + (size_t)rloc * D) + col, val);
    }
}

extern "C" void kernel_launch(void* const* d_in, const int* in_sizes, int n_in,
                              void* d_out, int out_size)
{
    const float* att_out  = (const float*)d_in[0];
    const float* duration = (const float*)d_in[1];
    const void*  alpha    = d_in[2];

    lr_fused_kernel<<<B * BLOCKS_PER_BATCH, 256>>>(att_out, duration, alpha,
                                                   (float*)d_out);
}

// round 4
// speedup vs baseline: 1.6244x; 1.0215x over previous
#include <cuda_runtime.h>
#include <cuda_bf16.h>
#include <math.h>

#define B 32
#define L 256
#define D 512
#define MAX_LEN 2048          // L * MAX_DUR(8)
#define ROWS_PB 64            // output rows per block
#define BLOCKS_PER_BATCH (MAX_LEN / ROWS_PB)   // 32
#define ROWS_PT (ROWS_PB / 2) // 32 consecutive rows per thread-group

// ---------------------------------------------------------------------------
// Fused length-regulator. Each block: recompute per-batch scan (cheap),
// derive source index for its 64 output rows, then expand-copy with
// run-length register reuse (idx sequence is monotone; avg run ~4 rows,
// so ~75% of gather loads are skipped entirely).
// Grid = 1024 blocks x 256 threads.
// ---------------------------------------------------------------------------
__global__ void __launch_bounds__(256)
lr_fused_kernel(const float* __restrict__ att_out,
                const float* __restrict__ duration,
                const void*  __restrict__ alpha_ptr,
                float* __restrict__ out)
{
    const int b        = blockIdx.x / BLOCKS_PER_BATCH;
    const int row_base = (blockIdx.x % BLOCKS_PER_BATCH) * ROWS_PB;
    const int t    = threadIdx.x;       // 0..255
    const int lane = t & 31;
    const int wid  = t >> 5;            // 0..7

    // --- resolve alpha (int32 or float32, bit-sniffed) ---
    int   ab = *(const int*)alpha_ptr;
    float af = __int_as_float(ab);
    float alpha = (fabsf(af) >= 1e-30f && fabsf(af) <= 1e30f) ? af : (float)ab;

    // --- round (rintf = round-half-even, matches jnp.round) ---
    int r = (int)rintf(__ldg(&duration[b * L + t]) * alpha);

    // --- inclusive scan over 256 values ---
    int v = r;
    #pragma unroll
    for (int off = 1; off < 32; off <<= 1) {
        int n = __shfl_up_sync(0xffffffffu, v, off);
        if (lane >= off) v += n;
    }
    __shared__ int warp_tot[8];
    __shared__ int warp_pre[8];
    if (lane == 31) warp_tot[wid] = v;
    __syncthreads();
    if (t < 8) {
        int wv = warp_tot[t];
        #pragma unroll
        for (int off = 1; off < 8; off <<= 1) {
            int n = __shfl_up_sync(0xffu, wv, off);
            if (t >= off) wv += n;
        }
        warp_pre[t] = wv;
    }
    __syncthreads();
    int csum = v + (wid > 0 ? warp_pre[wid - 1] : 0);

    __shared__ int s_csum[L];
    s_csum[t] = csum;
    __syncthreads();

    const int total = s_csum[L - 1];

    // --- per-row source index for this block's 64 rows (-1 = masked) ---
    __shared__ int s_idx[ROWS_PB];
    if (t < ROWS_PB) {
        int pos = row_base + t;
        int outi;
        if (pos >= total) {
            outi = -1;
        } else {
            int lo = 0, hi = L;             // first i with csum[i] > pos
            while (lo < hi) {
                int mid = (lo + hi) >> 1;
                if (s_csum[mid] > pos) hi = mid; else lo = mid + 1;
            }
            outi = lo < (L - 1) ? lo : (L - 1);
        }
        s_idx[t] = outi;
    }
    __syncthreads();

    // --- expand copy with run-length register reuse ---
    // Thread owns one float4 column, walks 32 CONSECUTIVE rows.
    // idx per row is warp-uniform (row same across warp), branches uniform.
    const int rl  = t >> 7;                 // 0/1: which 32-row half
    const int col = t & 127;                // float4 column
    const int r0  = rl * ROWS_PT;

    const float4* src = (const float4*)(att_out + (size_t)b * L * D) + col;
    float4*       dst = (float4*)(out + ((size_t)b * MAX_LEN + row_base + r0) * D) + col;

    const float4 zero = make_float4(0.f, 0.f, 0.f, 0.f);

    int    cur_idx = s_idx[r0];
    float4 cur     = zero;
    if (cur_idx >= 0) cur = __ldg(src + (size_t)cur_idx * (D / 4));

    #pragma unroll 4
    for (int rr = 0; rr < ROWS_PT; rr++) {
        int nidx = (rr < ROWS_PT - 1) ? s_idx[r0 + rr + 1] : -1;
        float4 nxt;
        if (nidx < 0)              nxt = zero;
        else if (nidx == cur_idx)  nxt = cur;
        else                       nxt = __ldg(src + (size_t)nidx * (D / 4));
        // store current row (load of next row already in flight)
        __stcs(dst + (size_t)rr * (D / 4), cur);
        cur = nxt;
        cur_idx = nidx;
    }
}

extern "C" void kernel_launch(void* const* d_in, const int* in_sizes, int n_in,
                              void* d_out, int out_size)
{
    const float* att_out  = (const float*)d_in[0];
    const float* duration = (const float*)d_in[1];
    const void*  alpha    = d_in[2];

    lr_fused_kernel<<<B * BLOCKS_PER_BATCH, 256>>>(att_out, duration, alpha,
                                                   (float*)d_out);
}

// round 5
// speedup vs baseline: 1.7299x; 1.0650x over previous
#include <cuda_runtime.h>
#include <cuda_bf16.h>
#include <math.h>

#define B 32
#define L 256
#define D 512
#define MAX_LEN 2048          // L * MAX_DUR(8)
#define ROWS_PB 64            // output rows per block
#define BLOCKS_PER_BATCH (MAX_LEN / ROWS_PB)   // 32
#define CHAIN 16              // rows per independent chain (2 chains/thread)

// ---------------------------------------------------------------------------
// Fused length-regulator. Per block: recompute per-batch scan (cheap),
// derive source indices for its 64 output rows, then expand-copy.
// Each thread owns one float4 column and walks TWO independent 16-row
// chains interleaved (2x MLP vs one 32-row chain), with run-length
// register reuse within each chain.
// Grid = 1024 blocks x 256 threads.
// ---------------------------------------------------------------------------
__global__ void __launch_bounds__(256)
lr_fused_kernel(const float* __restrict__ att_out,
                const float* __restrict__ duration,
                const void*  __restrict__ alpha_ptr,
                float* __restrict__ out)
{
    const int b        = blockIdx.x / BLOCKS_PER_BATCH;
    const int row_base = (blockIdx.x % BLOCKS_PER_BATCH) * ROWS_PB;
    const int t    = threadIdx.x;       // 0..255
    const int lane = t & 31;
    const int wid  = t >> 5;            // 0..7

    // --- resolve alpha (int32 or float32, bit-sniffed) ---
    int   ab = *(const int*)alpha_ptr;
    float af = __int_as_float(ab);
    float alpha = (fabsf(af) >= 1e-30f && fabsf(af) <= 1e30f) ? af : (float)ab;

    // --- round (rintf = round-half-even, matches jnp.round) ---
    int r = (int)rintf(__ldg(&duration[b * L + t]) * alpha);

    // --- inclusive scan over 256 values ---
    int v = r;
    #pragma unroll
    for (int off = 1; off < 32; off <<= 1) {
        int n = __shfl_up_sync(0xffffffffu, v, off);
        if (lane >= off) v += n;
    }
    __shared__ int warp_tot[8];
    __shared__ int warp_pre[8];
    if (lane == 31) warp_tot[wid] = v;
    __syncthreads();
    if (t < 8) {
        int wv = warp_tot[t];
        #pragma unroll
        for (int off = 1; off < 8; off <<= 1) {
            int n = __shfl_up_sync(0xffu, wv, off);
            if (t >= off) wv += n;
        }
        warp_pre[t] = wv;
    }
    __syncthreads();
    int csum = v + (wid > 0 ? warp_pre[wid - 1] : 0);

    __shared__ int s_csum[L];
    s_csum[t] = csum;
    __syncthreads();

    const int total = s_csum[L - 1];

    // --- per-row source index for this block's 64 rows (-1 = masked) ---
    __shared__ int s_idx[ROWS_PB];
    if (t < ROWS_PB) {
        int pos = row_base + t;
        int outi;
        if (pos >= total) {
            outi = -1;
        } else {
            int lo = 0, hi = L;             // first i with csum[i] > pos
            while (lo < hi) {
                int mid = (lo + hi) >> 1;
                if (s_csum[mid] > pos) hi = mid; else lo = mid + 1;
            }
            outi = lo < (L - 1) ? lo : (L - 1);
        }
        s_idx[t] = outi;
    }
    __syncthreads();

    // --- expand copy: 2 independent 16-row chains per thread ---
    const int rl  = t >> 7;                 // 0/1: which 32-row half
    const int col = t & 127;                // float4 column
    const int r0  = rl * 2 * CHAIN;         // chain0 base row (within block)
    const int r1  = r0 + CHAIN;             // chain1 base row

    const float4* src = (const float4*)(att_out + (size_t)b * L * D) + col;
    float4* dst0 = (float4*)(out + ((size_t)b * MAX_LEN + row_base + r0) * D) + col;
    float4* dst1 = (float4*)(out + ((size_t)b * MAX_LEN + row_base + r1) * D) + col;

    const float4 zero = make_float4(0.f, 0.f, 0.f, 0.f);

    int    i0 = s_idx[r0];
    int    i1 = s_idx[r1];
    float4 c0 = (i0 >= 0) ? __ldg(src + (size_t)i0 * (D / 4)) : zero;
    float4 c1 = (i1 >= 0) ? __ldg(src + (size_t)i1 * (D / 4)) : zero;

    #pragma unroll
    for (int rr = 0; rr < CHAIN; rr++) {
        int n0 = (rr < CHAIN - 1) ? s_idx[r0 + rr + 1] : -1;
        int n1 = (rr < CHAIN - 1) ? s_idx[r1 + rr + 1] : -1;

        float4 x0, x1;
        if (n0 < 0)          x0 = zero;
        else if (n0 == i0)   x0 = c0;
        else                 x0 = __ldg(src + (size_t)n0 * (D / 4));
        if (n1 < 0)          x1 = zero;
        else if (n1 == i1)   x1 = c1;
        else                 x1 = __ldg(src + (size_t)n1 * (D / 4));

        // store current rows (next-row loads already in flight)
        __stcs(dst0 + (size_t)rr * (D / 4), c0);
        __stcs(dst1 + (size_t)rr * (D / 4), c1);

        c0 = x0; i0 = n0;
        c1 = x1; i1 = n1;
    }
}

extern "C" void kernel_launch(void* const* d_in, const int* in_sizes, int n_in,
                              void* d_out, int out_size)
{
    const float* att_out  = (const float*)d_in[0];
    const float* duration = (const float*)d_in[1];
    const void*  alpha    = d_in[2];

    lr_fused_kernel<<<B * BLOCKS_PER_BATCH, 256>>>(att_out, duration, alpha,
                                                   (float*)d_out);
}

// round 6
// speedup vs baseline: 1.7366x; 1.0038x over previous
#include <cuda_runtime.h>
#include <cuda_bf16.h>
#include <math.h>

#define B 32
#define L 256
#define D 512
#define MAX_LEN 2048                     // L * MAX_DUR(8)
#define ROWS_PB 32                       // output rows per block
#define BLOCKS_PER_BATCH (MAX_LEN / ROWS_PB)   // 64
#define F4_PER_ROW (D / 4)               // 128
#define ELEMS_PB (ROWS_PB * F4_PER_ROW)  // 4096 float4 per block
#define ELEMS_PT (ELEMS_PB / 256)        // 16 float4 per thread

// ---------------------------------------------------------------------------
// Fused length-regulator. Per block: recompute per-batch scan (cheap, hidden
// by other resident CTAs), derive source index for its 32 output rows, then
// a flat unrolled copy of 16 INDEPENDENT float4 load->store pairs per thread
// (max MLP, no register-carried dependency chain, no branchy run detection).
// Grid = 2048 blocks x 256 threads.
// ---------------------------------------------------------------------------
__global__ void __launch_bounds__(256)
lr_fused_kernel(const float* __restrict__ att_out,
                const float* __restrict__ duration,
                const void*  __restrict__ alpha_ptr,
                float* __restrict__ out)
{
    const int b        = blockIdx.x / BLOCKS_PER_BATCH;
    const int row_base = (blockIdx.x % BLOCKS_PER_BATCH) * ROWS_PB;
    const int t    = threadIdx.x;       // 0..255
    const int lane = t & 31;
    const int wid  = t >> 5;            // 0..7

    // --- resolve alpha (int32 or float32, bit-sniffed) ---
    int   ab = *(const int*)alpha_ptr;
    float af = __int_as_float(ab);
    float alpha = (fabsf(af) >= 1e-30f && fabsf(af) <= 1e30f) ? af : (float)ab;

    // --- round (rintf = round-half-even, matches jnp.round) ---
    int r = (int)rintf(__ldg(&duration[b * L + t]) * alpha);

    // --- inclusive scan over 256 values ---
    int v = r;
    #pragma unroll
    for (int off = 1; off < 32; off <<= 1) {
        int n = __shfl_up_sync(0xffffffffu, v, off);
        if (lane >= off) v += n;
    }
    __shared__ int warp_tot[8];
    __shared__ int warp_pre[8];
    if (lane == 31) warp_tot[wid] = v;
    __syncthreads();
    if (t < 8) {
        int wv = warp_tot[t];
        #pragma unroll
        for (int off = 1; off < 8; off <<= 1) {
            int n = __shfl_up_sync(0xffu, wv, off);
            if (t >= off) wv += n;
        }
        warp_pre[t] = wv;
    }
    __syncthreads();
    int csum = v + (wid > 0 ? warp_pre[wid - 1] : 0);

    __shared__ int s_csum[L];
    s_csum[t] = csum;
    __syncthreads();

    const int total = s_csum[L - 1];

    // --- per-row source index for this block's 32 rows (-1 = masked) ---
    __shared__ int s_idx[ROWS_PB];
    if (t < ROWS_PB) {
        int pos = row_base + t;
        int outi;
        if (pos >= total) {
            outi = -1;
        } else {
            int lo = 0, hi = L;             // first i with csum[i] > pos
            while (lo < hi) {
                int mid = (lo + hi) >> 1;
                if (s_csum[mid] > pos) hi = mid; else lo = mid + 1;
            }
            outi = lo < (L - 1) ? lo : (L - 1);
        }
        s_idx[t] = outi;
    }
    __syncthreads();

    // --- flat expand copy: 16 independent float4 copies per thread ---
    const float4* __restrict__ src = (const float4*)(att_out + (size_t)b * L * D);
    float4* __restrict__ dst =
        (float4*)(out + ((size_t)b * MAX_LEN + row_base) * D);
    const float4 zero = make_float4(0.f, 0.f, 0.f, 0.f);

    #pragma unroll
    for (int k = 0; k < ELEMS_PT; k++) {
        int e   = k * 256 + t;              // 0..4095 within block chunk
        int row = e >> 7;                   // local output row
        int col = e & (F4_PER_ROW - 1);
        int idx = s_idx[row];
        float4 val = (idx >= 0)
                   ? __ldg(src + (size_t)idx * F4_PER_ROW + col)
                   : zero;
        __stcs(dst + e, val);
    }
}

extern "C" void kernel_launch(void* const* d_in, const int* in_sizes, int n_in,
                              void* d_out, int out_size)
{
    const float* att_out  = (const float*)d_in[0];
    const float* duration = (const float*)d_in[1];
    const void*  alpha    = d_in[2];

    lr_fused_kernel<<<B * BLOCKS_PER_BATCH, 256>>>(att_out, duration, alpha,
                                                   (float*)d_out);
}